// round 1
// baseline (speedup 1.0000x reference)
#include <cuda_runtime.h>
#include <math_constants.h>

#define N_NODES 50000
#define N_EDGES 1600000
#define ET      (N_EDGES + N_NODES)
#define HID     128
#define NG      512

// ---------------- scratch (device globals; allocation-free) ----------------
__device__ float g_h[(size_t)N_NODES * HID];    // GEMM output / message features
__device__ float g_agg[(size_t)N_NODES * HID];  // aggregated output of a GAT layer
__device__ float g_asrc[N_NODES];
__device__ float g_adst[N_NODES];
__device__ int   g_rowptr[N_NODES + 1];
__device__ int   g_cursor[N_NODES];             // doubles as degree histogram
__device__ int   g_csrc[ET];                    // src ids sorted by dst (CSR)
__device__ float g_maxp[NG * HID];
__device__ float g_sump[NG * HID];
__device__ int   g_cnt[NG];

// ---------------- CSR build ----------------
__global__ void zero_deg_kernel() {
    int i = blockIdx.x * blockDim.x + threadIdx.x;
    if (i < N_NODES) g_cursor[i] = 0;
}

__global__ void hist_kernel(const int* __restrict__ ei) {
    int e = blockIdx.x * blockDim.x + threadIdx.x;
    if (e >= ET) return;
    int d = (e < N_EDGES) ? ei[N_EDGES + e] : (e - N_EDGES);
    atomicAdd(&g_cursor[d], 1);
}

__global__ void scan_kernel() {
    // exclusive scan of g_cursor (degrees) into g_rowptr; single block of 1024
    __shared__ int sh[32];
    int t = threadIdx.x, lane = t & 31, wid = t >> 5;
    int run = 0;
    for (int base = 0; base < N_NODES; base += 1024) {
        int idx = base + t;
        int v = (idx < N_NODES) ? g_cursor[idx] : 0;
        int x = v;
#pragma unroll
        for (int o = 1; o < 32; o <<= 1) {
            int y = __shfl_up_sync(0xffffffffu, x, o);
            if (lane >= o) x += y;
        }
        if (lane == 31) sh[wid] = x;
        __syncthreads();
        if (wid == 0) {
            int y = sh[lane];
#pragma unroll
            for (int o = 1; o < 32; o <<= 1) {
                int z = __shfl_up_sync(0xffffffffu, y, o);
                if (lane >= o) y += z;
            }
            sh[lane] = y;
        }
        __syncthreads();
        int offs = wid ? sh[wid - 1] : 0;
        int total = sh[31];
        if (idx < N_NODES) g_rowptr[idx] = run + offs + x - v;
        run += total;
        __syncthreads();
    }
    if (t == 0) g_rowptr[N_NODES] = run;
}

__global__ void cursor_copy_kernel() {
    int i = blockIdx.x * blockDim.x + threadIdx.x;
    if (i < N_NODES) g_cursor[i] = g_rowptr[i];
}

__global__ void scatter_kernel(const int* __restrict__ ei) {
    int e = blockIdx.x * blockDim.x + threadIdx.x;
    if (e >= ET) return;
    int s, d;
    if (e < N_EDGES) { s = ei[e]; d = ei[N_EDGES + e]; }
    else             { s = d = e - N_EDGES; }
    int pos = atomicAdd(&g_cursor[d], 1);
    g_csrc[pos] = s;
}

// ---------------- GEMM: g_h = relu(A) @ W, A is [N,128], W is [128,128] ----
// A_ext == nullptr means A = g_agg (layer 2 input).
__global__ __launch_bounds__(256) void gemm_relu128(const float* __restrict__ A_ext,
                                                    const float* __restrict__ W) {
    const float* __restrict__ A = A_ext ? A_ext : g_agg;
    __shared__ float As[128 * 36];  // [row][k0..k0+31], stride 36 (pad)
    __shared__ float Ws[32 * 128];  // [k][col]
    const int tid = threadIdx.x;
    const int row0 = blockIdx.x * 128;
    const int tx = tid & 15, ty = tid >> 4;

    float acc[8][8];
#pragma unroll
    for (int i = 0; i < 8; i++)
#pragma unroll
        for (int j = 0; j < 8; j++) acc[i][j] = 0.f;

    for (int k0 = 0; k0 < 128; k0 += 32) {
        // load A tile (relu applied), 1024 float4s
#pragma unroll
        for (int i = 0; i < 4; i++) {
            int f = tid + i * 256;
            int r = f >> 3, kq = f & 7;
            int gr = row0 + r;
            float4 v = make_float4(0.f, 0.f, 0.f, 0.f);
            if (gr < N_NODES) v = *(const float4*)(A + (size_t)gr * HID + k0 + kq * 4);
            v.x = fmaxf(v.x, 0.f); v.y = fmaxf(v.y, 0.f);
            v.z = fmaxf(v.z, 0.f); v.w = fmaxf(v.w, 0.f);
            *(float4*)(&As[r * 36 + kq * 4]) = v;
        }
        // load W tile
#pragma unroll
        for (int i = 0; i < 4; i++) {
            int f = tid + i * 256;
            int kk = f >> 5, cq = f & 31;
            float4 v = *(const float4*)(W + (size_t)(k0 + kk) * HID + cq * 4);
            *(float4*)(&Ws[kk * 128 + cq * 4]) = v;
        }
        __syncthreads();
#pragma unroll
        for (int k = 0; k < 32; k++) {
            float a[8], b[8];
#pragma unroll
            for (int i = 0; i < 8; i++) a[i] = As[(ty + 16 * i) * 36 + k];
#pragma unroll
            for (int j = 0; j < 8; j++) b[j] = Ws[k * 128 + tx + 16 * j];
#pragma unroll
            for (int i = 0; i < 8; i++)
#pragma unroll
                for (int j = 0; j < 8; j++) acc[i][j] = fmaf(a[i], b[j], acc[i][j]);
        }
        __syncthreads();
    }
#pragma unroll
    for (int i = 0; i < 8; i++) {
        int gr = row0 + ty + 16 * i;
        if (gr >= N_NODES) break;
#pragma unroll
        for (int j = 0; j < 8; j++) g_h[(size_t)gr * HID + tx + 16 * j] = acc[i][j];
    }
}

// ---------------- asrc/adst = h @ a_src, h @ a_dst ----------------
__global__ void attvec_kernel(const float* __restrict__ av, const float* __restrict__ adv) {
    int w = (blockIdx.x * blockDim.x + threadIdx.x) >> 5;
    int lane = threadIdx.x & 31;
    if (w >= N_NODES) return;
    float4 hv = *(const float4*)(&g_h[(size_t)w * HID + lane * 4]);
    float4 a1 = *(const float4*)(av + lane * 4);
    float4 a2 = *(const float4*)(adv + lane * 4);
    float s1 = hv.x * a1.x + hv.y * a1.y + hv.z * a1.z + hv.w * a1.w;
    float s2 = hv.x * a2.x + hv.y * a2.y + hv.z * a2.z + hv.w * a2.w;
#pragma unroll
    for (int o = 16; o; o >>= 1) {
        s1 += __shfl_xor_sync(0xffffffffu, s1, o);
        s2 += __shfl_xor_sync(0xffffffffu, s2, o);
    }
    if (lane == 0) { g_asrc[w] = s1; g_adst[w] = s2; }
}

// ---------------- GAT aggregation: warp per dst node, online softmax -------
__global__ __launch_bounds__(256) void gat_agg_kernel(const float* __restrict__ bias) {
    int w = (blockIdx.x * blockDim.x + threadIdx.x) >> 5;
    int lane = threadIdx.x & 31;
    if (w >= N_NODES) return;
    int beg = g_rowptr[w], end = g_rowptr[w + 1];
    float ad = g_adst[w];

    // phase 1: per-lane online (max, sum), then warp merge
    float m = -CUDART_INF_F, ssum = 0.f;
    for (int j = beg + lane; j < end; j += 32) {
        int s = g_csrc[j];
        float l = g_asrc[s] + ad;
        l = l > 0.f ? l : 0.2f * l;
        if (l > m) { ssum = ssum * __expf(m - l) + 1.f; m = l; }
        else       { ssum += __expf(l - m); }
    }
#pragma unroll
    for (int o = 16; o; o >>= 1) {
        float m2 = __shfl_xor_sync(0xffffffffu, m, o);
        float s2 = __shfl_xor_sync(0xffffffffu, ssum, o);
        float mn = fmaxf(m, m2);
        float p1 = (ssum > 0.f) ? ssum * __expf(m - mn) : 0.f;
        float p2 = (s2 > 0.f) ? s2 * __expf(m2 - mn) : 0.f;
        ssum = p1 + p2; m = mn;
    }
    float inv = 1.f / ssum;

    // phase 2: weighted gather of h[src]
    float4 acc = make_float4(0.f, 0.f, 0.f, 0.f);
    for (int j = beg; j < end; j++) {
        int s = g_csrc[j];                 // uniform across warp -> broadcast
        float l = g_asrc[s] + ad;
        l = l > 0.f ? l : 0.2f * l;
        float alpha = __expf(l - m) * inv;
        float4 hv = *(const float4*)(&g_h[(size_t)s * HID + (lane << 2)]);
        acc.x = fmaf(alpha, hv.x, acc.x);
        acc.y = fmaf(alpha, hv.y, acc.y);
        acc.z = fmaf(alpha, hv.z, acc.z);
        acc.w = fmaf(alpha, hv.w, acc.w);
    }
    float4 bv = *(const float4*)(bias + (lane << 2));
    *(float4*)(&g_agg[(size_t)w * HID + (lane << 2)]) =
        make_float4(acc.x + bv.x, acc.y + bv.y, acc.z + bv.z, acc.w + bv.w);
}

// ---------------- pooling ----------------
__global__ void pool_zero_kernel() {
    int i = blockIdx.x * blockDim.x + threadIdx.x;
    if (i < NG * HID) { g_maxp[i] = 0.f; g_sump[i] = 0.f; }
    if (i < NG) g_cnt[i] = 0;
}

__global__ void pool_kernel(const int* __restrict__ batch) {
    int w = (blockIdx.x * blockDim.x + threadIdx.x) >> 5;
    int lane = threadIdx.x & 31;
    if (w >= N_NODES) return;
    int g = batch[w];
    float4 v = *(const float4*)(&g_agg[(size_t)w * HID + (lane << 2)]);
    v.x = fmaxf(v.x, 0.f); v.y = fmaxf(v.y, 0.f);
    v.z = fmaxf(v.z, 0.f); v.w = fmaxf(v.w, 0.f);
    int base = g * HID + (lane << 2);
    // values >= 0: float ordering == int ordering of bit patterns, init 0 is valid
    atomicMax((int*)&g_maxp[base + 0], __float_as_int(v.x));
    atomicMax((int*)&g_maxp[base + 1], __float_as_int(v.y));
    atomicMax((int*)&g_maxp[base + 2], __float_as_int(v.z));
    atomicMax((int*)&g_maxp[base + 3], __float_as_int(v.w));
    atomicAdd(&g_sump[base + 0], v.x);
    atomicAdd(&g_sump[base + 1], v.y);
    atomicAdd(&g_sump[base + 2], v.z);
    atomicAdd(&g_sump[base + 3], v.w);
    if (lane == 0) atomicAdd(&g_cnt[g], 1);
}

__global__ void final_kernel(const float* __restrict__ fcw, const float* __restrict__ fcb,
                             float* __restrict__ out) {
    int w = (blockIdx.x * blockDim.x + threadIdx.x) >> 5;
    int lane = threadIdx.x & 31;
    if (w >= NG) return;
    float4 mx = *(const float4*)(&g_maxp[w * HID + (lane << 2)]);
    float4 sm = *(const float4*)(&g_sump[w * HID + (lane << 2)]);
    float4 w1 = *(const float4*)(fcw + (lane << 2));
    float4 w2 = *(const float4*)(fcw + HID + (lane << 2));
    float c = fmaxf((float)g_cnt[w], 1.f);
    float p = mx.x * w1.x + mx.y * w1.y + mx.z * w1.z + mx.w * w1.w
            + (sm.x * w2.x + sm.y * w2.y + sm.z * w2.z + sm.w * w2.w) / c;
#pragma unroll
    for (int o = 16; o; o >>= 1) p += __shfl_xor_sync(0xffffffffu, p, o);
    if (lane == 0) out[w] = p + fcb[0];
}

// ---------------- launch ----------------
extern "C" void kernel_launch(void* const* d_in, const int* in_sizes, int n_in,
                              void* d_out, int out_size) {
    const float* x   = (const float*)d_in[0];
    const int*   ei  = (const int*)d_in[1];
    const int*   bat = (const int*)d_in[2];
    const float* W1  = (const float*)d_in[3];
    const float* as1 = (const float*)d_in[4];
    const float* ad1 = (const float*)d_in[5];
    const float* b1  = (const float*)d_in[6];
    const float* W2  = (const float*)d_in[7];
    const float* as2 = (const float*)d_in[8];
    const float* ad2 = (const float*)d_in[9];
    const float* b2  = (const float*)d_in[10];
    const float* fcw = (const float*)d_in[11];
    const float* fcb = (const float*)d_in[12];
    float* out = (float*)d_out;

    const int TB = 256;
    const int nodeBlocks = (N_NODES + TB - 1) / TB;
    const int edgeBlocks = (ET + TB - 1) / TB;
    const int warpNodeBlocks = ((size_t)N_NODES * 32 + TB - 1) / TB;
    const int gemmBlocks = (N_NODES + 127) / 128;

    // CSR build (once; shared by both layers)
    zero_deg_kernel<<<nodeBlocks, TB>>>();
    hist_kernel<<<edgeBlocks, TB>>>(ei);
    scan_kernel<<<1, 1024>>>();
    cursor_copy_kernel<<<nodeBlocks, TB>>>();
    scatter_kernel<<<edgeBlocks, TB>>>(ei);

    // layer 1
    gemm_relu128<<<gemmBlocks, TB>>>(x, W1);
    attvec_kernel<<<warpNodeBlocks, TB>>>(as1, ad1);
    gat_agg_kernel<<<warpNodeBlocks, TB>>>(b1);

    // layer 2 (A = g_agg via nullptr)
    gemm_relu128<<<gemmBlocks, TB>>>(nullptr, W2);
    attvec_kernel<<<warpNodeBlocks, TB>>>(as2, ad2);
    gat_agg_kernel<<<warpNodeBlocks, TB>>>(b2);

    // pooling + head
    pool_zero_kernel<<<(NG * HID + TB - 1) / TB, TB>>>();
    pool_kernel<<<warpNodeBlocks, TB>>>(bat);
    final_kernel<<<(NG * 32 + TB - 1) / TB, TB>>>(fcw, fcb, out);
}

// round 3
// speedup vs baseline: 1.1256x; 1.1256x over previous
#include <cuda_runtime.h>
#include <math_constants.h>

#define N_NODES 50000
#define N_EDGES 1600000
#define ET      (N_EDGES + N_NODES)
#define HID     128
#define NG      512

// ---------------- scratch (device globals; allocation-free) ----------------
__device__ float g_h[(size_t)N_NODES * HID];    // message features (fp32)
__device__ float g_agg[(size_t)N_NODES * HID];  // layer-1 aggregation output
__device__ float g_asrc[N_NODES];
__device__ float g_adst[N_NODES];
__device__ int   g_rowptr[N_NODES + 1];
__device__ int   g_cursor[N_NODES];             // degree histogram / scatter cursor
__device__ int   g_csrc[ET];                    // src ids grouped by dst (CSR)
__device__ float g_maxp[NG * HID];
__device__ float g_sump[NG * HID];
__device__ int   g_cnt[NG];

// ---------------- init: zero hist + pooling buffers ----------------
__global__ void init_kernel() {
    int i = blockIdx.x * blockDim.x + threadIdx.x;
    if (i < N_NODES) g_cursor[i] = 0;
    if (i < NG * HID) { g_maxp[i] = 0.f; g_sump[i] = 0.f; }
    if (i < NG) g_cnt[i] = 0;
}

__global__ void hist_kernel(const int* __restrict__ ei) {
    int e = blockIdx.x * blockDim.x + threadIdx.x;
    if (e >= ET) return;
    int d = (e < N_EDGES) ? ei[N_EDGES + e] : (e - N_EDGES);
    atomicAdd(&g_cursor[d], 1);
}

__global__ void scan_kernel() {
    // exclusive scan of degrees -> g_rowptr AND g_cursor (scatter cursor)
    __shared__ int sh[32];
    int t = threadIdx.x, lane = t & 31, wid = t >> 5;
    int run = 0;
    for (int base = 0; base < N_NODES; base += 1024) {
        int idx = base + t;
        int v = (idx < N_NODES) ? g_cursor[idx] : 0;
        int x = v;
#pragma unroll
        for (int o = 1; o < 32; o <<= 1) {
            int y = __shfl_up_sync(0xffffffffu, x, o);
            if (lane >= o) x += y;
        }
        if (lane == 31) sh[wid] = x;
        __syncthreads();
        if (wid == 0) {
            int y = sh[lane];
#pragma unroll
            for (int o = 1; o < 32; o <<= 1) {
                int z = __shfl_up_sync(0xffffffffu, y, o);
                if (lane >= o) y += z;
            }
            sh[lane] = y;
        }
        __syncthreads();
        int offs = wid ? sh[wid - 1] : 0;
        int total = sh[31];
        if (idx < N_NODES) {
            int ex = run + offs + x - v;
            g_rowptr[idx] = ex;
            g_cursor[idx] = ex;
        }
        run += total;
        __syncthreads();
    }
    if (t == 0) g_rowptr[N_NODES] = run;
}

__global__ void scatter_kernel(const int* __restrict__ ei) {
    int e = blockIdx.x * blockDim.x + threadIdx.x;
    if (e >= ET) return;
    int s, d;
    if (e < N_EDGES) { s = ei[e]; d = ei[N_EDGES + e]; }
    else             { s = d = e - N_EDGES; }
    int pos = atomicAdd(&g_cursor[d], 1);
    g_csrc[pos] = s;
}

// ---------------- GEMM: g_h = relu(A) @ W, A [N,128], W [128,128] ----------
// A_ext == nullptr -> A = g_agg (layer 2 input).
__global__ __launch_bounds__(256) void gemm_relu128(const float* __restrict__ A_ext,
                                                    const float* __restrict__ W) {
    const float* __restrict__ A = A_ext ? A_ext : g_agg;
    __shared__ float As[128 * 36];  // [row][k], pad 36
    __shared__ float Ws[32 * 132];  // [k][col], pad 132 (16B-aligned rows)
    const int tid = threadIdx.x;
    const int row0 = blockIdx.x * 128;
    const int tx = tid & 15, ty = tid >> 4;   // cols: tx*4+{0..3}, 64+tx*4+{0..3}
                                              // rows: ty*4+{0..3}, 64+ty*4+{0..3}
    float acc[8][8];
#pragma unroll
    for (int i = 0; i < 8; i++)
#pragma unroll
        for (int j = 0; j < 8; j++) acc[i][j] = 0.f;

    for (int k0 = 0; k0 < 128; k0 += 32) {
#pragma unroll
        for (int i = 0; i < 4; i++) {
            int f = tid + i * 256;
            int r = f >> 3, kq = f & 7;
            int gr = row0 + r;
            float4 v = make_float4(0.f, 0.f, 0.f, 0.f);
            if (gr < N_NODES) v = *(const float4*)(A + (size_t)gr * HID + k0 + kq * 4);
            v.x = fmaxf(v.x, 0.f); v.y = fmaxf(v.y, 0.f);
            v.z = fmaxf(v.z, 0.f); v.w = fmaxf(v.w, 0.f);
            *(float4*)(&As[r * 36 + kq * 4]) = v;
        }
#pragma unroll
        for (int i = 0; i < 4; i++) {
            int f = tid + i * 256;
            int kk = f >> 5, cq = f & 31;
            float4 v = *(const float4*)(W + (size_t)(k0 + kk) * HID + cq * 4);
            *(float4*)(&Ws[kk * 132 + cq * 4]) = v;
        }
        __syncthreads();
#pragma unroll
        for (int k = 0; k < 32; k++) {
            float a[8];
#pragma unroll
            for (int i = 0; i < 4; i++) {
                a[i]     = As[(ty * 4 + i) * 36 + k];
                a[4 + i] = As[(64 + ty * 4 + i) * 36 + k];
            }
            float4 b0 = *(const float4*)(&Ws[k * 132 + tx * 4]);
            float4 b1 = *(const float4*)(&Ws[k * 132 + 64 + tx * 4]);
            float b[8] = {b0.x, b0.y, b0.z, b0.w, b1.x, b1.y, b1.z, b1.w};
#pragma unroll
            for (int i = 0; i < 8; i++)
#pragma unroll
                for (int j = 0; j < 8; j++) acc[i][j] = fmaf(a[i], b[j], acc[i][j]);
        }
        __syncthreads();
    }
#pragma unroll
    for (int i = 0; i < 8; i++) {
        int gr = row0 + (i < 4 ? ty * 4 + i : 64 + ty * 4 + (i - 4));
        if (gr >= N_NODES) continue;
        float4 v0 = make_float4(acc[i][0], acc[i][1], acc[i][2], acc[i][3]);
        float4 v1 = make_float4(acc[i][4], acc[i][5], acc[i][6], acc[i][7]);
        *(float4*)(&g_h[(size_t)gr * HID + tx * 4])      = v0;
        *(float4*)(&g_h[(size_t)gr * HID + 64 + tx * 4]) = v1;
    }
}

// ---------------- asrc/adst = h @ a_src, h @ a_dst ----------------
__global__ void attvec_kernel(const float* __restrict__ av, const float* __restrict__ adv) {
    int w = (blockIdx.x * blockDim.x + threadIdx.x) >> 5;
    int lane = threadIdx.x & 31;
    if (w >= N_NODES) return;
    float4 hv = *(const float4*)(&g_h[(size_t)w * HID + lane * 4]);
    float4 a1 = *(const float4*)(av + lane * 4);
    float4 a2 = *(const float4*)(adv + lane * 4);
    float s1 = hv.x * a1.x + hv.y * a1.y + hv.z * a1.z + hv.w * a1.w;
    float s2 = hv.x * a2.x + hv.y * a2.y + hv.z * a2.z + hv.w * a2.w;
#pragma unroll
    for (int o = 16; o; o >>= 1) {
        s1 += __shfl_xor_sync(0xffffffffu, s1, o);
        s2 += __shfl_xor_sync(0xffffffffu, s2, o);
    }
    if (lane == 0) { g_asrc[w] = s1; g_adst[w] = s2; }
}

// ------ GAT aggregation: warp per dst node, online softmax -----------------
// pool_mode=0: write g_agg (fp32). pool_mode=1: relu + pooling atomics.
__global__ __launch_bounds__(256) void gat_agg_kernel(const float* __restrict__ bias,
                                                      const int* __restrict__ batch,
                                                      int pool_mode) {
    int w = (blockIdx.x * blockDim.x + threadIdx.x) >> 5;
    int lane = threadIdx.x & 31;
    if (w >= N_NODES) return;
    int beg = g_rowptr[w], end = g_rowptr[w + 1];
    float ad = g_adst[w];

    // phase 1: per-lane online (max, sum), then warp merge
    float m = -CUDART_INF_F, ssum = 0.f;
    for (int j = beg + lane; j < end; j += 32) {
        int s = g_csrc[j];
        float l = g_asrc[s] + ad;
        l = l > 0.f ? l : 0.2f * l;
        if (l > m) { ssum = ssum * __expf(m - l) + 1.f; m = l; }
        else       { ssum += __expf(l - m); }
    }
#pragma unroll
    for (int o = 16; o; o >>= 1) {
        float m2 = __shfl_xor_sync(0xffffffffu, m, o);
        float s2 = __shfl_xor_sync(0xffffffffu, ssum, o);
        float mn = fmaxf(m, m2);
        float p1 = (ssum > 0.f) ? ssum * __expf(m - mn) : 0.f;
        float p2 = (s2 > 0.f) ? s2 * __expf(m2 - mn) : 0.f;
        ssum = p1 + p2; m = mn;
    }
    float inv = 1.f / ssum;

    // phase 2: weighted gather of h[src], fp32 accumulate
    float4 acc = make_float4(0.f, 0.f, 0.f, 0.f);
    for (int j = beg; j < end; j++) {
        int s = g_csrc[j];                 // uniform across warp -> broadcast
        float l = g_asrc[s] + ad;
        l = l > 0.f ? l : 0.2f * l;
        float alpha = __expf(l - m) * inv;
        float4 hv = *(const float4*)(&g_h[(size_t)s * HID + (lane << 2)]);
        acc.x = fmaf(alpha, hv.x, acc.x);
        acc.y = fmaf(alpha, hv.y, acc.y);
        acc.z = fmaf(alpha, hv.z, acc.z);
        acc.w = fmaf(alpha, hv.w, acc.w);
    }
    float4 bv = *(const float4*)(bias + (lane << 2));
    acc.x += bv.x; acc.y += bv.y; acc.z += bv.z; acc.w += bv.w;

    if (!pool_mode) {
        *(float4*)(&g_agg[(size_t)w * HID + (lane << 2)]) = acc;
    } else {
        acc.x = fmaxf(acc.x, 0.f); acc.y = fmaxf(acc.y, 0.f);
        acc.z = fmaxf(acc.z, 0.f); acc.w = fmaxf(acc.w, 0.f);
        int g = batch[w];
        int base = g * HID + (lane << 2);
        // values >= 0: int ordering of float bits is valid, init 0 is valid
        atomicMax((int*)&g_maxp[base + 0], __float_as_int(acc.x));
        atomicMax((int*)&g_maxp[base + 1], __float_as_int(acc.y));
        atomicMax((int*)&g_maxp[base + 2], __float_as_int(acc.z));
        atomicMax((int*)&g_maxp[base + 3], __float_as_int(acc.w));
        atomicAdd(&g_sump[base + 0], acc.x);
        atomicAdd(&g_sump[base + 1], acc.y);
        atomicAdd(&g_sump[base + 2], acc.z);
        atomicAdd(&g_sump[base + 3], acc.w);
        if (lane == 0) atomicAdd(&g_cnt[g], 1);
    }
}

__global__ void final_kernel(const float* __restrict__ fcw, const float* __restrict__ fcb,
                             float* __restrict__ out) {
    int w = (blockIdx.x * blockDim.x + threadIdx.x) >> 5;
    int lane = threadIdx.x & 31;
    if (w >= NG) return;
    float4 mx = *(const float4*)(&g_maxp[w * HID + (lane << 2)]);
    float4 sm = *(const float4*)(&g_sump[w * HID + (lane << 2)]);
    float4 w1 = *(const float4*)(fcw + (lane << 2));
    float4 w2 = *(const float4*)(fcw + HID + (lane << 2));
    float c = fmaxf((float)g_cnt[w], 1.f);
    float p = mx.x * w1.x + mx.y * w1.y + mx.z * w1.z + mx.w * w1.w
            + (sm.x * w2.x + sm.y * w2.y + sm.z * w2.z + sm.w * w2.w) / c;
#pragma unroll
    for (int o = 16; o; o >>= 1) p += __shfl_xor_sync(0xffffffffu, p, o);
    if (lane == 0) out[w] = p + fcb[0];
}

// ---------------- launch ----------------
extern "C" void kernel_launch(void* const* d_in, const int* in_sizes, int n_in,
                              void* d_out, int out_size) {
    const float* x   = (const float*)d_in[0];
    const int*   ei  = (const int*)d_in[1];
    const int*   bat = (const int*)d_in[2];
    const float* W1  = (const float*)d_in[3];
    const float* as1 = (const float*)d_in[4];
    const float* ad1 = (const float*)d_in[5];
    const float* b1  = (const float*)d_in[6];
    const float* W2  = (const float*)d_in[7];
    const float* as2 = (const float*)d_in[8];
    const float* ad2 = (const float*)d_in[9];
    const float* b2  = (const float*)d_in[10];
    const float* fcw = (const float*)d_in[11];
    const float* fcb = (const float*)d_in[12];
    float* out = (float*)d_out;

    const int TB = 256;
    const int initBlocks = (NG * HID + TB - 1) / TB;
    const int edgeBlocks = (ET + TB - 1) / TB;
    const int warpNodeBlocks = (N_NODES * 32 + TB - 1) / TB;
    const int gemmBlocks = (N_NODES + 127) / 128;

    init_kernel<<<initBlocks, TB>>>();                 // 1
    hist_kernel<<<edgeBlocks, TB>>>(ei);               // 2
    scan_kernel<<<1, 1024>>>();                        // 3
    gemm_relu128<<<gemmBlocks, TB>>>(x, W1);           // 4 (profiler slot)
    scatter_kernel<<<edgeBlocks, TB>>>(ei);            // 5
    attvec_kernel<<<warpNodeBlocks, TB>>>(as1, ad1);   // 6
    gat_agg_kernel<<<warpNodeBlocks, TB>>>(b1, bat, 0);// 7

    gemm_relu128<<<gemmBlocks, TB>>>(nullptr, W2);     // 8
    attvec_kernel<<<warpNodeBlocks, TB>>>(as2, ad2);   // 9
    gat_agg_kernel<<<warpNodeBlocks, TB>>>(b2, bat, 1);// 10 (fused pooling)

    final_kernel<<<(NG * 32 + TB - 1) / TB, TB>>>(fcw, fcb, out); // 11
}

// round 4
// speedup vs baseline: 1.2813x; 1.1383x over previous
#include <cuda_runtime.h>
#include <cuda_fp16.h>
#include <math_constants.h>

#define N_NODES 50000
#define N_EDGES 1600000
#define ET      (N_EDGES + N_NODES)
#define HID     128
#define NG      512

// ---------------- scratch (device globals; allocation-free) ----------------
__device__ __half g_hh[(size_t)N_NODES * HID];  // message features (fp16, gather path)
__device__ float g_agg[(size_t)N_NODES * HID];  // layer-1 aggregation output (fp32)
__device__ float g_asrc[N_NODES];
__device__ float g_adst[N_NODES];
__device__ int   g_rowptr[N_NODES + 1];
__device__ int   g_cursor[N_NODES];
__device__ int   g_csrc[ET];
__device__ float g_maxp[NG * HID];
__device__ float g_sump[NG * HID];
__device__ int   g_cnt[NG];

// ---------------- f32x2 packed helpers ----------------
__device__ __forceinline__ unsigned long long fma2(unsigned long long a,
                                                   unsigned long long b,
                                                   unsigned long long c) {
    unsigned long long d;
    asm("fma.rn.f32x2 %0, %1, %2, %3;" : "=l"(d) : "l"(a), "l"(b), "l"(c));
    return d;
}
__device__ __forceinline__ unsigned long long pack2(float lo, float hi) {
    unsigned long long r;
    asm("mov.b64 %0, {%1, %2};" : "=l"(r) : "f"(lo), "f"(hi));
    return r;
}
__device__ __forceinline__ void unpack2(unsigned long long v, float& lo, float& hi) {
    asm("mov.b64 {%0, %1}, %2;" : "=f"(lo), "=f"(hi) : "l"(v));
}

// ---------------- init ----------------
__global__ void init_kernel() {
    int i = blockIdx.x * blockDim.x + threadIdx.x;
    if (i < N_NODES) g_cursor[i] = 0;
    if (i < NG * HID) { g_maxp[i] = 0.f; g_sump[i] = 0.f; }
    if (i < NG) g_cnt[i] = 0;
}

__global__ void hist_kernel(const int* __restrict__ ei) {
    int e = blockIdx.x * blockDim.x + threadIdx.x;
    if (e >= ET) return;
    int d = (e < N_EDGES) ? ei[N_EDGES + e] : (e - N_EDGES);
    atomicAdd(&g_cursor[d], 1);
}

__global__ void scan_kernel() {
    __shared__ int sh[32];
    int t = threadIdx.x, lane = t & 31, wid = t >> 5;
    int run = 0;
    for (int base = 0; base < N_NODES; base += 1024) {
        int idx = base + t;
        int v = (idx < N_NODES) ? g_cursor[idx] : 0;
        int x = v;
#pragma unroll
        for (int o = 1; o < 32; o <<= 1) {
            int y = __shfl_up_sync(0xffffffffu, x, o);
            if (lane >= o) x += y;
        }
        if (lane == 31) sh[wid] = x;
        __syncthreads();
        if (wid == 0) {
            int y = sh[lane];
#pragma unroll
            for (int o = 1; o < 32; o <<= 1) {
                int z = __shfl_up_sync(0xffffffffu, y, o);
                if (lane >= o) y += z;
            }
            sh[lane] = y;
        }
        __syncthreads();
        int offs = wid ? sh[wid - 1] : 0;
        int total = sh[31];
        if (idx < N_NODES) {
            int ex = run + offs + x - v;
            g_rowptr[idx] = ex;
            g_cursor[idx] = ex;
        }
        run += total;
        __syncthreads();
    }
    if (t == 0) g_rowptr[N_NODES] = run;
}

__global__ void scatter_kernel(const int* __restrict__ ei) {
    int e = blockIdx.x * blockDim.x + threadIdx.x;
    if (e >= ET) return;
    int s, d;
    if (e < N_EDGES) { s = ei[e]; d = ei[N_EDGES + e]; }
    else             { s = d = e - N_EDGES; }
    int pos = atomicAdd(&g_cursor[d], 1);
    g_csrc[pos] = s;
}

// -------- fused GEMM: h = relu(A)@W (fp16 out) + asrc/adst epilogue --------
// A_ext == nullptr -> A = g_agg.
__global__ __launch_bounds__(256, 2) void gemm_fused(const float* __restrict__ A_ext,
                                                     const float* __restrict__ W,
                                                     const float* __restrict__ av,
                                                     const float* __restrict__ adv) {
    const float* __restrict__ A = A_ext ? A_ext : g_agg;
    __shared__ float As[128 * 36];  // [row][k], pad 36
    __shared__ float Ws[32 * 132];  // [k][col], pad 132
    const int tid = threadIdx.x;
    const int row0 = blockIdx.x * 128;
    const int tx = tid & 15, ty = tid >> 4;
    // thread rows: ty*4+{0..3}, 64+ty*4+{0..3}; cols: tx*4+{0..3}, 64+tx*4+{0..3}

    unsigned long long acc2[8][4];
#pragma unroll
    for (int i = 0; i < 8; i++)
#pragma unroll
        for (int j = 0; j < 4; j++) acc2[i][j] = 0ull;

    for (int k0 = 0; k0 < 128; k0 += 32) {
#pragma unroll
        for (int i = 0; i < 4; i++) {
            int f = tid + i * 256;
            int r = f >> 3, kq = f & 7;
            int gr = row0 + r;
            float4 v = make_float4(0.f, 0.f, 0.f, 0.f);
            if (gr < N_NODES) v = *(const float4*)(A + (size_t)gr * HID + k0 + kq * 4);
            v.x = fmaxf(v.x, 0.f); v.y = fmaxf(v.y, 0.f);
            v.z = fmaxf(v.z, 0.f); v.w = fmaxf(v.w, 0.f);
            *(float4*)(&As[r * 36 + kq * 4]) = v;
        }
#pragma unroll
        for (int i = 0; i < 4; i++) {
            int f = tid + i * 256;
            int kk = f >> 5, cq = f & 31;
            float4 v = *(const float4*)(W + (size_t)(k0 + kk) * HID + cq * 4);
            *(float4*)(&Ws[kk * 132 + cq * 4]) = v;
        }
        __syncthreads();
#pragma unroll
        for (int k = 0; k < 32; k++) {
            float4 b0 = *(const float4*)(&Ws[k * 132 + tx * 4]);
            float4 b1 = *(const float4*)(&Ws[k * 132 + 64 + tx * 4]);
            unsigned long long bb[4];
            bb[0] = pack2(b0.x, b0.y); bb[1] = pack2(b0.z, b0.w);
            bb[2] = pack2(b1.x, b1.y); bb[3] = pack2(b1.z, b1.w);
#pragma unroll
            for (int i = 0; i < 8; i++) {
                float a = (i < 4) ? As[(ty * 4 + i) * 36 + k]
                                  : As[(64 + ty * 4 + (i - 4)) * 36 + k];
                unsigned long long aa = pack2(a, a);
#pragma unroll
                for (int j = 0; j < 4; j++) acc2[i][j] = fma2(aa, bb[j], acc2[i][j]);
            }
        }
        __syncthreads();
    }

    // epilogue: fp16 store + in-register asrc/adst (exact fp32 logits)
    float4 a1lo = *(const float4*)(av + tx * 4);
    float4 a1hi = *(const float4*)(av + 64 + tx * 4);
    float4 a2lo = *(const float4*)(adv + tx * 4);
    float4 a2hi = *(const float4*)(adv + 64 + tx * 4);
    const unsigned fullm = 0xffffffffu;
#pragma unroll
    for (int i = 0; i < 8; i++) {
        int gr = row0 + ((i < 4) ? (ty * 4 + i) : (64 + ty * 4 + (i - 4)));
        float c0, c1, c2, c3, c4, c5, c6, c7;
        unpack2(acc2[i][0], c0, c1); unpack2(acc2[i][1], c2, c3);
        unpack2(acc2[i][2], c4, c5); unpack2(acc2[i][3], c6, c7);
        float s1 = c0 * a1lo.x + c1 * a1lo.y + c2 * a1lo.z + c3 * a1lo.w
                 + c4 * a1hi.x + c5 * a1hi.y + c6 * a1hi.z + c7 * a1hi.w;
        float s2 = c0 * a2lo.x + c1 * a2lo.y + c2 * a2lo.z + c3 * a2lo.w
                 + c4 * a2hi.x + c5 * a2hi.y + c6 * a2hi.z + c7 * a2hi.w;
#pragma unroll
        for (int o = 8; o; o >>= 1) {
            s1 += __shfl_xor_sync(fullm, s1, o);
            s2 += __shfl_xor_sync(fullm, s2, o);
        }
        if (gr < N_NODES) {
            if (tx == 0) { g_asrc[gr] = s1; g_adst[gr] = s2; }
            __half2 h0 = __floats2half2_rn(c0, c1);
            __half2 h1 = __floats2half2_rn(c2, c3);
            __half2 h2 = __floats2half2_rn(c4, c5);
            __half2 h3 = __floats2half2_rn(c6, c7);
            uint2 u0 = make_uint2(*(unsigned*)&h0, *(unsigned*)&h1);
            uint2 u1 = make_uint2(*(unsigned*)&h2, *(unsigned*)&h3);
            *(uint2*)(g_hh + (size_t)gr * HID + tx * 4)      = u0;
            *(uint2*)(g_hh + (size_t)gr * HID + 64 + tx * 4) = u1;
        }
    }
}

// ------ GAT aggregation: warp per dst node, online softmax, fp16 gather ----
// pool_mode=0: write g_agg (fp32). pool_mode=1: relu + pooling atomics.
__global__ __launch_bounds__(256) void gat_agg_kernel(const float* __restrict__ bias,
                                                      const int* __restrict__ batch,
                                                      int pool_mode) {
    int w = (blockIdx.x * blockDim.x + threadIdx.x) >> 5;
    int lane = threadIdx.x & 31;
    if (w >= N_NODES) return;
    int beg = g_rowptr[w], end = g_rowptr[w + 1];
    float ad = g_adst[w];

    float m = -CUDART_INF_F, ssum = 0.f;
    for (int j = beg + lane; j < end; j += 32) {
        int s = g_csrc[j];
        float l = g_asrc[s] + ad;
        l = l > 0.f ? l : 0.2f * l;
        if (l > m) { ssum = ssum * __expf(m - l) + 1.f; m = l; }
        else       { ssum += __expf(l - m); }
    }
#pragma unroll
    for (int o = 16; o; o >>= 1) {
        float m2 = __shfl_xor_sync(0xffffffffu, m, o);
        float s2 = __shfl_xor_sync(0xffffffffu, ssum, o);
        float mn = fmaxf(m, m2);
        float p1 = (ssum > 0.f) ? ssum * __expf(m - mn) : 0.f;
        float p2 = (s2 > 0.f) ? s2 * __expf(m2 - mn) : 0.f;
        ssum = p1 + p2; m = mn;
    }
    float inv = 1.f / ssum;

    float4 acc = make_float4(0.f, 0.f, 0.f, 0.f);
    for (int j = beg; j < end; j++) {
        int s = g_csrc[j];                 // uniform across warp
        float l = g_asrc[s] + ad;
        l = l > 0.f ? l : 0.2f * l;
        float alpha = __expf(l - m) * inv;
        uint2 u = *(const uint2*)(g_hh + (size_t)s * HID + (lane << 2));
        float2 f0 = __half22float2(*(__half2*)&u.x);
        float2 f1 = __half22float2(*(__half2*)&u.y);
        acc.x = fmaf(alpha, f0.x, acc.x);
        acc.y = fmaf(alpha, f0.y, acc.y);
        acc.z = fmaf(alpha, f1.x, acc.z);
        acc.w = fmaf(alpha, f1.y, acc.w);
    }
    float4 bv = *(const float4*)(bias + (lane << 2));
    acc.x += bv.x; acc.y += bv.y; acc.z += bv.z; acc.w += bv.w;

    if (!pool_mode) {
        *(float4*)(&g_agg[(size_t)w * HID + (lane << 2)]) = acc;
    } else {
        acc.x = fmaxf(acc.x, 0.f); acc.y = fmaxf(acc.y, 0.f);
        acc.z = fmaxf(acc.z, 0.f); acc.w = fmaxf(acc.w, 0.f);
        int g = batch[w];
        int base = g * HID + (lane << 2);
        atomicMax((int*)&g_maxp[base + 0], __float_as_int(acc.x));
        atomicMax((int*)&g_maxp[base + 1], __float_as_int(acc.y));
        atomicMax((int*)&g_maxp[base + 2], __float_as_int(acc.z));
        atomicMax((int*)&g_maxp[base + 3], __float_as_int(acc.w));
        atomicAdd(&g_sump[base + 0], acc.x);
        atomicAdd(&g_sump[base + 1], acc.y);
        atomicAdd(&g_sump[base + 2], acc.z);
        atomicAdd(&g_sump[base + 3], acc.w);
        if (lane == 0) atomicAdd(&g_cnt[g], 1);
    }
}

__global__ void final_kernel(const float* __restrict__ fcw, const float* __restrict__ fcb,
                             float* __restrict__ out) {
    int w = (blockIdx.x * blockDim.x + threadIdx.x) >> 5;
    int lane = threadIdx.x & 31;
    if (w >= NG) return;
    float4 mx = *(const float4*)(&g_maxp[w * HID + (lane << 2)]);
    float4 sm = *(const float4*)(&g_sump[w * HID + (lane << 2)]);
    float4 w1 = *(const float4*)(fcw + (lane << 2));
    float4 w2 = *(const float4*)(fcw + HID + (lane << 2));
    float c = fmaxf((float)g_cnt[w], 1.f);
    float p = mx.x * w1.x + mx.y * w1.y + mx.z * w1.z + mx.w * w1.w
            + (sm.x * w2.x + sm.y * w2.y + sm.z * w2.z + sm.w * w2.w) / c;
#pragma unroll
    for (int o = 16; o; o >>= 1) p += __shfl_xor_sync(0xffffffffu, p, o);
    if (lane == 0) out[w] = p + fcb[0];
}

// ---------------- launch ----------------
extern "C" void kernel_launch(void* const* d_in, const int* in_sizes, int n_in,
                              void* d_out, int out_size) {
    const float* x   = (const float*)d_in[0];
    const int*   ei  = (const int*)d_in[1];
    const int*   bat = (const int*)d_in[2];
    const float* W1  = (const float*)d_in[3];
    const float* as1 = (const float*)d_in[4];
    const float* ad1 = (const float*)d_in[5];
    const float* b1  = (const float*)d_in[6];
    const float* W2  = (const float*)d_in[7];
    const float* as2 = (const float*)d_in[8];
    const float* ad2 = (const float*)d_in[9];
    const float* b2  = (const float*)d_in[10];
    const float* fcw = (const float*)d_in[11];
    const float* fcb = (const float*)d_in[12];
    float* out = (float*)d_out;

    const int TB = 256;
    const int initBlocks = (NG * HID + TB - 1) / TB;
    const int edgeBlocks = (ET + TB - 1) / TB;
    const int warpNodeBlocks = (N_NODES * 32 + TB - 1) / TB;
    const int gemmBlocks = (N_NODES + 127) / 128;

    init_kernel<<<initBlocks, TB>>>();                    // 1
    hist_kernel<<<edgeBlocks, TB>>>(ei);                  // 2
    scan_kernel<<<1, 1024>>>();                           // 3
    gemm_fused<<<gemmBlocks, TB>>>(x, W1, as1, ad1);      // 4 (profiler slot)
    scatter_kernel<<<edgeBlocks, TB>>>(ei);               // 5
    gat_agg_kernel<<<warpNodeBlocks, TB>>>(b1, bat, 0);   // 6

    gemm_fused<<<gemmBlocks, TB>>>(nullptr, W2, as2, ad2);// 7
    gat_agg_kernel<<<warpNodeBlocks, TB>>>(b2, bat, 1);   // 8 (fused pooling)

    final_kernel<<<(NG * 32 + TB - 1) / TB, TB>>>(fcw, fcb, out); // 9
}

// round 5
// speedup vs baseline: 1.3972x; 1.0905x over previous
#include <cuda_runtime.h>
#include <cuda_fp16.h>
#include <math_constants.h>

#define N_NODES 50000
#define N_EDGES 1600000
#define ET      (N_EDGES + N_NODES)
#define HID     128
#define NG      512
#define DEG_CAP 64

// ---------------- scratch (device globals; allocation-free) ----------------
__device__ __half g_hh[(size_t)N_NODES * HID];  // message features (fp16, gather path)
__device__ float g_agg[(size_t)N_NODES * HID];  // layer-1 aggregation output (fp32)
__device__ float g_asrc[N_NODES];
__device__ float g_adst[N_NODES];
__device__ int   g_rowptr[N_NODES + 1];
__device__ int   g_cursor[N_NODES];
__device__ int   g_csrc[ET];
__device__ float g_maxp[NG * HID];
__device__ float g_sump[NG * HID];
__device__ int   g_cnt[NG];

// ---------------- f32x2 packed helpers ----------------
__device__ __forceinline__ unsigned long long fma2(unsigned long long a,
                                                   unsigned long long b,
                                                   unsigned long long c) {
    unsigned long long d;
    asm("fma.rn.f32x2 %0, %1, %2, %3;" : "=l"(d) : "l"(a), "l"(b), "l"(c));
    return d;
}
__device__ __forceinline__ unsigned long long pack2(float lo, float hi) {
    unsigned long long r;
    asm("mov.b64 %0, {%1, %2};" : "=l"(r) : "f"(lo), "f"(hi));
    return r;
}
__device__ __forceinline__ void unpack2(unsigned long long v, float& lo, float& hi) {
    asm("mov.b64 {%0, %1}, %2;" : "=f"(lo), "=f"(hi) : "l"(v));
}

// ---------------- init ----------------
__global__ void init_kernel() {
    int i = blockIdx.x * blockDim.x + threadIdx.x;
    if (i < N_NODES) g_cursor[i] = 0;
    if (i < NG * HID) { g_maxp[i] = 0.f; g_sump[i] = 0.f; }
    if (i < NG) g_cnt[i] = 0;
}

__global__ void hist_kernel(const int* __restrict__ ei) {
    int e = blockIdx.x * blockDim.x + threadIdx.x;
    if (e >= ET) return;
    int d = (e < N_EDGES) ? ei[N_EDGES + e] : (e - N_EDGES);
    atomicAdd(&g_cursor[d], 1);
}

__global__ void scan_kernel() {
    __shared__ int sh[32];
    int t = threadIdx.x, lane = t & 31, wid = t >> 5;
    int run = 0;
    for (int base = 0; base < N_NODES; base += 1024) {
        int idx = base + t;
        int v = (idx < N_NODES) ? g_cursor[idx] : 0;
        int x = v;
#pragma unroll
        for (int o = 1; o < 32; o <<= 1) {
            int y = __shfl_up_sync(0xffffffffu, x, o);
            if (lane >= o) x += y;
        }
        if (lane == 31) sh[wid] = x;
        __syncthreads();
        if (wid == 0) {
            int y = sh[lane];
#pragma unroll
            for (int o = 1; o < 32; o <<= 1) {
                int z = __shfl_up_sync(0xffffffffu, y, o);
                if (lane >= o) y += z;
            }
            sh[lane] = y;
        }
        __syncthreads();
        int offs = wid ? sh[wid - 1] : 0;
        int total = sh[31];
        if (idx < N_NODES) {
            int ex = run + offs + x - v;
            g_rowptr[idx] = ex;
            g_cursor[idx] = ex;
        }
        run += total;
        __syncthreads();
    }
    if (t == 0) g_rowptr[N_NODES] = run;
}

__global__ void scatter_kernel(const int* __restrict__ ei) {
    int e = blockIdx.x * blockDim.x + threadIdx.x;
    if (e >= ET) return;
    int s, d;
    if (e < N_EDGES) { s = ei[e]; d = ei[N_EDGES + e]; }
    else             { s = d = e - N_EDGES; }
    int pos = atomicAdd(&g_cursor[d], 1);
    g_csrc[pos] = s;
}

// -------- fused GEMM: h = relu(A)@W (fp16 out) + asrc/adst epilogue --------
__global__ __launch_bounds__(256, 2) void gemm_fused(const float* __restrict__ A_ext,
                                                     const float* __restrict__ W,
                                                     const float* __restrict__ av,
                                                     const float* __restrict__ adv) {
    const float* __restrict__ A = A_ext ? A_ext : g_agg;
    __shared__ float As[128 * 36];
    __shared__ float Ws[32 * 132];
    const int tid = threadIdx.x;
    const int row0 = blockIdx.x * 128;
    const int tx = tid & 15, ty = tid >> 4;

    unsigned long long acc2[8][4];
#pragma unroll
    for (int i = 0; i < 8; i++)
#pragma unroll
        for (int j = 0; j < 4; j++) acc2[i][j] = 0ull;

    for (int k0 = 0; k0 < 128; k0 += 32) {
#pragma unroll
        for (int i = 0; i < 4; i++) {
            int f = tid + i * 256;
            int r = f >> 3, kq = f & 7;
            int gr = row0 + r;
            float4 v = make_float4(0.f, 0.f, 0.f, 0.f);
            if (gr < N_NODES) v = *(const float4*)(A + (size_t)gr * HID + k0 + kq * 4);
            v.x = fmaxf(v.x, 0.f); v.y = fmaxf(v.y, 0.f);
            v.z = fmaxf(v.z, 0.f); v.w = fmaxf(v.w, 0.f);
            *(float4*)(&As[r * 36 + kq * 4]) = v;
        }
#pragma unroll
        for (int i = 0; i < 4; i++) {
            int f = tid + i * 256;
            int kk = f >> 5, cq = f & 31;
            float4 v = *(const float4*)(W + (size_t)(k0 + kk) * HID + cq * 4);
            *(float4*)(&Ws[kk * 132 + cq * 4]) = v;
        }
        __syncthreads();
#pragma unroll
        for (int k = 0; k < 32; k++) {
            float4 b0 = *(const float4*)(&Ws[k * 132 + tx * 4]);
            float4 b1 = *(const float4*)(&Ws[k * 132 + 64 + tx * 4]);
            unsigned long long bb[4];
            bb[0] = pack2(b0.x, b0.y); bb[1] = pack2(b0.z, b0.w);
            bb[2] = pack2(b1.x, b1.y); bb[3] = pack2(b1.z, b1.w);
#pragma unroll
            for (int i = 0; i < 8; i++) {
                float a = (i < 4) ? As[(ty * 4 + i) * 36 + k]
                                  : As[(64 + ty * 4 + (i - 4)) * 36 + k];
                unsigned long long aa = pack2(a, a);
#pragma unroll
                for (int j = 0; j < 4; j++) acc2[i][j] = fma2(aa, bb[j], acc2[i][j]);
            }
        }
        __syncthreads();
    }

    float4 a1lo = *(const float4*)(av + tx * 4);
    float4 a1hi = *(const float4*)(av + 64 + tx * 4);
    float4 a2lo = *(const float4*)(adv + tx * 4);
    float4 a2hi = *(const float4*)(adv + 64 + tx * 4);
    const unsigned fullm = 0xffffffffu;
#pragma unroll
    for (int i = 0; i < 8; i++) {
        int gr = row0 + ((i < 4) ? (ty * 4 + i) : (64 + ty * 4 + (i - 4)));
        float c0, c1, c2, c3, c4, c5, c6, c7;
        unpack2(acc2[i][0], c0, c1); unpack2(acc2[i][1], c2, c3);
        unpack2(acc2[i][2], c4, c5); unpack2(acc2[i][3], c6, c7);
        float s1 = c0 * a1lo.x + c1 * a1lo.y + c2 * a1lo.z + c3 * a1lo.w
                 + c4 * a1hi.x + c5 * a1hi.y + c6 * a1hi.z + c7 * a1hi.w;
        float s2 = c0 * a2lo.x + c1 * a2lo.y + c2 * a2lo.z + c3 * a2lo.w
                 + c4 * a2hi.x + c5 * a2hi.y + c6 * a2hi.z + c7 * a2hi.w;
#pragma unroll
        for (int o = 8; o; o >>= 1) {
            s1 += __shfl_xor_sync(fullm, s1, o);
            s2 += __shfl_xor_sync(fullm, s2, o);
        }
        if (gr < N_NODES) {
            if (tx == 0) { g_asrc[gr] = s1; g_adst[gr] = s2; }
            __half2 h0 = __floats2half2_rn(c0, c1);
            __half2 h1 = __floats2half2_rn(c2, c3);
            __half2 h2 = __floats2half2_rn(c4, c5);
            __half2 h3 = __floats2half2_rn(c6, c7);
            uint2 u0 = make_uint2(*(unsigned*)&h0, *(unsigned*)&h1);
            uint2 u1 = make_uint2(*(unsigned*)&h2, *(unsigned*)&h3);
            *(uint2*)(g_hh + (size_t)gr * HID + tx * 4)      = u0;
            *(uint2*)(g_hh + (size_t)gr * HID + 64 + tx * 4) = u1;
        }
    }
}

// ------ GAT aggregation: warp/node, 2-pass softmax, shared alphas, x4 unroll
__global__ __launch_bounds__(256) void gat_agg_kernel(const float* __restrict__ bias,
                                                      const int* __restrict__ batch,
                                                      int pool_mode) {
    __shared__ float shw[8][DEG_CAP];
    int w = (blockIdx.x * blockDim.x + threadIdx.x) >> 5;
    int lane = threadIdx.x & 31;
    int wid = (threadIdx.x >> 5) & 7;
    if (w >= N_NODES) return;
    int beg = g_rowptr[w], end = g_rowptr[w + 1];
    int n = end - beg;
    float ad = g_adst[w];

    // pass A: max of leaky logits (no exp)
    float m = -CUDART_INF_F;
    for (int i = lane; i < n; i += 32) {
        int s = g_csrc[beg + i];
        float l = g_asrc[s] + ad;
        l = l > 0.f ? l : 0.2f * l;
        m = fmaxf(m, l);
    }
#pragma unroll
    for (int o = 16; o; o >>= 1) m = fmaxf(m, __shfl_xor_sync(0xffffffffu, m, o));

    // pass B: exp + sum; stash unnormalized weights in shared (common case)
    bool small = (n <= DEG_CAP);
    float ssum = 0.f;
    for (int i = lane; i < n; i += 32) {
        int s = g_csrc[beg + i];
        float l = g_asrc[s] + ad;
        l = l > 0.f ? l : 0.2f * l;
        float e = __expf(l - m);
        ssum += e;
        if (small) shw[wid][i] = e;
    }
#pragma unroll
    for (int o = 16; o; o >>= 1) ssum += __shfl_xor_sync(0xffffffffu, ssum, o);
    float inv = 1.f / ssum;
    __syncwarp();

    // phase 2: gather Σ e * h[src]  (scale by inv once at the end)
    float4 acc = make_float4(0.f, 0.f, 0.f, 0.f);
    const int col = lane << 2;
    if (small) {
        int i = 0;
        for (; i + 4 <= n; i += 4) {
            int s0 = g_csrc[beg + i + 0];
            int s1 = g_csrc[beg + i + 1];
            int s2 = g_csrc[beg + i + 2];
            int s3 = g_csrc[beg + i + 3];
            float e0 = shw[wid][i + 0], e1 = shw[wid][i + 1];
            float e2 = shw[wid][i + 2], e3 = shw[wid][i + 3];
            uint2 u0 = *(const uint2*)(g_hh + (size_t)s0 * HID + col);
            uint2 u1 = *(const uint2*)(g_hh + (size_t)s1 * HID + col);
            uint2 u2 = *(const uint2*)(g_hh + (size_t)s2 * HID + col);
            uint2 u3 = *(const uint2*)(g_hh + (size_t)s3 * HID + col);
            float2 f0a = __half22float2(*(__half2*)&u0.x), f0b = __half22float2(*(__half2*)&u0.y);
            float2 f1a = __half22float2(*(__half2*)&u1.x), f1b = __half22float2(*(__half2*)&u1.y);
            float2 f2a = __half22float2(*(__half2*)&u2.x), f2b = __half22float2(*(__half2*)&u2.y);
            float2 f3a = __half22float2(*(__half2*)&u3.x), f3b = __half22float2(*(__half2*)&u3.y);
            acc.x = fmaf(e0, f0a.x, acc.x); acc.y = fmaf(e0, f0a.y, acc.y);
            acc.z = fmaf(e0, f0b.x, acc.z); acc.w = fmaf(e0, f0b.y, acc.w);
            acc.x = fmaf(e1, f1a.x, acc.x); acc.y = fmaf(e1, f1a.y, acc.y);
            acc.z = fmaf(e1, f1b.x, acc.z); acc.w = fmaf(e1, f1b.y, acc.w);
            acc.x = fmaf(e2, f2a.x, acc.x); acc.y = fmaf(e2, f2a.y, acc.y);
            acc.z = fmaf(e2, f2b.x, acc.z); acc.w = fmaf(e2, f2b.y, acc.w);
            acc.x = fmaf(e3, f3a.x, acc.x); acc.y = fmaf(e3, f3a.y, acc.y);
            acc.z = fmaf(e3, f3b.x, acc.z); acc.w = fmaf(e3, f3b.y, acc.w);
        }
        for (; i < n; i++) {
            int s = g_csrc[beg + i];
            float e = shw[wid][i];
            uint2 u = *(const uint2*)(g_hh + (size_t)s * HID + col);
            float2 fa = __half22float2(*(__half2*)&u.x);
            float2 fb = __half22float2(*(__half2*)&u.y);
            acc.x = fmaf(e, fa.x, acc.x); acc.y = fmaf(e, fa.y, acc.y);
            acc.z = fmaf(e, fb.x, acc.z); acc.w = fmaf(e, fb.y, acc.w);
        }
    } else {  // rare high-degree path: recompute weights inline
        for (int i = 0; i < n; i++) {
            int s = g_csrc[beg + i];
            float l = g_asrc[s] + ad;
            l = l > 0.f ? l : 0.2f * l;
            float e = __expf(l - m);
            uint2 u = *(const uint2*)(g_hh + (size_t)s * HID + col);
            float2 fa = __half22float2(*(__half2*)&u.x);
            float2 fb = __half22float2(*(__half2*)&u.y);
            acc.x = fmaf(e, fa.x, acc.x); acc.y = fmaf(e, fa.y, acc.y);
            acc.z = fmaf(e, fb.x, acc.z); acc.w = fmaf(e, fb.y, acc.w);
        }
    }
    float4 bv = *(const float4*)(bias + col);
    acc.x = fmaf(acc.x, inv, bv.x);
    acc.y = fmaf(acc.y, inv, bv.y);
    acc.z = fmaf(acc.z, inv, bv.z);
    acc.w = fmaf(acc.w, inv, bv.w);

    if (!pool_mode) {
        *(float4*)(&g_agg[(size_t)w * HID + col]) = acc;
    } else {
        acc.x = fmaxf(acc.x, 0.f); acc.y = fmaxf(acc.y, 0.f);
        acc.z = fmaxf(acc.z, 0.f); acc.w = fmaxf(acc.w, 0.f);
        int g = batch[w];
        int base = g * HID + col;
        atomicMax((int*)&g_maxp[base + 0], __float_as_int(acc.x));
        atomicMax((int*)&g_maxp[base + 1], __float_as_int(acc.y));
        atomicMax((int*)&g_maxp[base + 2], __float_as_int(acc.z));
        atomicMax((int*)&g_maxp[base + 3], __float_as_int(acc.w));
        atomicAdd(&g_sump[base + 0], acc.x);
        atomicAdd(&g_sump[base + 1], acc.y);
        atomicAdd(&g_sump[base + 2], acc.z);
        atomicAdd(&g_sump[base + 3], acc.w);
        if (lane == 0) atomicAdd(&g_cnt[g], 1);
    }
}

__global__ void final_kernel(const float* __restrict__ fcw, const float* __restrict__ fcb,
                             float* __restrict__ out) {
    int w = (blockIdx.x * blockDim.x + threadIdx.x) >> 5;
    int lane = threadIdx.x & 31;
    if (w >= NG) return;
    float4 mx = *(const float4*)(&g_maxp[w * HID + (lane << 2)]);
    float4 sm = *(const float4*)(&g_sump[w * HID + (lane << 2)]);
    float4 w1 = *(const float4*)(fcw + (lane << 2));
    float4 w2 = *(const float4*)(fcw + HID + (lane << 2));
    float c = fmaxf((float)g_cnt[w], 1.f);
    float p = mx.x * w1.x + mx.y * w1.y + mx.z * w1.z + mx.w * w1.w
            + (sm.x * w2.x + sm.y * w2.y + sm.z * w2.z + sm.w * w2.w) / c;
#pragma unroll
    for (int o = 16; o; o >>= 1) p += __shfl_xor_sync(0xffffffffu, p, o);
    if (lane == 0) out[w] = p + fcb[0];
}

// ---------------- launch ----------------
extern "C" void kernel_launch(void* const* d_in, const int* in_sizes, int n_in,
                              void* d_out, int out_size) {
    const float* x   = (const float*)d_in[0];
    const int*   ei  = (const int*)d_in[1];
    const int*   bat = (const int*)d_in[2];
    const float* W1  = (const float*)d_in[3];
    const float* as1 = (const float*)d_in[4];
    const float* ad1 = (const float*)d_in[5];
    const float* b1  = (const float*)d_in[6];
    const float* W2  = (const float*)d_in[7];
    const float* as2 = (const float*)d_in[8];
    const float* ad2 = (const float*)d_in[9];
    const float* b2  = (const float*)d_in[10];
    const float* fcw = (const float*)d_in[11];
    const float* fcb = (const float*)d_in[12];
    float* out = (float*)d_out;

    const int TB = 256;
    const int initBlocks = (NG * HID + TB - 1) / TB;
    const int edgeBlocks = (ET + TB - 1) / TB;
    const int warpNodeBlocks = (N_NODES * 32 + TB - 1) / TB;
    const int gemmBlocks = (N_NODES + 127) / 128;

    init_kernel<<<initBlocks, TB>>>();                    // 1
    hist_kernel<<<edgeBlocks, TB>>>(ei);                  // 2
    scan_kernel<<<1, 1024>>>();                           // 3
    scatter_kernel<<<edgeBlocks, TB>>>(ei);               // 4 (profiler slot)
    gemm_fused<<<gemmBlocks, TB>>>(x, W1, as1, ad1);      // 5
    gat_agg_kernel<<<warpNodeBlocks, TB>>>(b1, bat, 0);   // 6

    gemm_fused<<<gemmBlocks, TB>>>(nullptr, W2, as2, ad2);// 7
    gat_agg_kernel<<<warpNodeBlocks, TB>>>(b2, bat, 1);   // 8 (fused pooling)

    final_kernel<<<(NG * 32 + TB - 1) / TB, TB>>>(fcw, fcb, out); // 9
}

// round 6
// speedup vs baseline: 1.5072x; 1.0787x over previous
#include <cuda_runtime.h>
#include <cuda_fp16.h>
#include <math_constants.h>

#define N_NODES 50000
#define N_EDGES 1600000
#define ET      (N_EDGES + N_NODES)
#define EQ      (N_EDGES / 4)
#define HID     128
#define NG      512
#define DEG_CAP 64

// ---------------- scratch (device globals; allocation-free) ----------------
__device__ __half g_hh[(size_t)N_NODES * HID];  // message features (fp16, gather path)
__device__ float g_agg[(size_t)N_NODES * HID];  // layer-1 aggregation output (fp32)
__device__ float g_asrc[N_NODES];
__device__ float g_adst[N_NODES];
__device__ int   g_rowptr[N_NODES + 1];
__device__ int   g_cursor[N_NODES];
__device__ int   g_csrc[ET];
__device__ float g_maxp[NG * HID];
__device__ float g_sump[NG * HID];
__device__ int   g_cnt[NG];

// ---------------- f32x2 packed helpers ----------------
__device__ __forceinline__ unsigned long long fma2(unsigned long long a,
                                                   unsigned long long b,
                                                   unsigned long long c) {
    unsigned long long d;
    asm("fma.rn.f32x2 %0, %1, %2, %3;" : "=l"(d) : "l"(a), "l"(b), "l"(c));
    return d;
}
__device__ __forceinline__ unsigned long long pack2(float lo, float hi) {
    unsigned long long r;
    asm("mov.b64 %0, {%1, %2};" : "=l"(r) : "f"(lo), "f"(hi));
    return r;
}
__device__ __forceinline__ void unpack2(unsigned long long v, float& lo, float& hi) {
    asm("mov.b64 {%0, %1}, %2;" : "=f"(lo), "=f"(hi) : "l"(v));
}

// ---------------- init: cursor=1 (self-loop pre-counted), pools zero -------
__global__ void init_kernel() {
    int i = blockIdx.x * blockDim.x + threadIdx.x;
    if (i < N_NODES) g_cursor[i] = 1;
    if (i < NG * HID) { g_maxp[i] = 0.f; g_sump[i] = 0.f; }
    if (i < NG) g_cnt[i] = 0;
}

// ---------------- histogram over real edges only (x4 unroll) ----------------
__global__ void hist_kernel(const int* __restrict__ ei) {
    int t = blockIdx.x * blockDim.x + threadIdx.x;
    if (t >= EQ) return;
    int4 d = *(const int4*)(ei + N_EDGES + t * 4);
    atomicAdd(&g_cursor[d.x], 1);
    atomicAdd(&g_cursor[d.y], 1);
    atomicAdd(&g_cursor[d.z], 1);
    atomicAdd(&g_cursor[d.w], 1);
}

__global__ void scan_kernel() {
    __shared__ int sh[32];
    int t = threadIdx.x, lane = t & 31, wid = t >> 5;
    int run = 0;
    for (int base = 0; base < N_NODES; base += 1024) {
        int idx = base + t;
        int v = (idx < N_NODES) ? g_cursor[idx] : 0;
        int x = v;
#pragma unroll
        for (int o = 1; o < 32; o <<= 1) {
            int y = __shfl_up_sync(0xffffffffu, x, o);
            if (lane >= o) x += y;
        }
        if (lane == 31) sh[wid] = x;
        __syncthreads();
        if (wid == 0) {
            int y = sh[lane];
#pragma unroll
            for (int o = 1; o < 32; o <<= 1) {
                int z = __shfl_up_sync(0xffffffffu, y, o);
                if (lane >= o) y += z;
            }
            sh[lane] = y;
        }
        __syncthreads();
        int offs = wid ? sh[wid - 1] : 0;
        int total = sh[31];
        if (idx < N_NODES) {
            int ex = run + offs + x - v;
            g_rowptr[idx] = ex;
            g_cursor[idx] = ex;
        }
        run += total;
        __syncthreads();
    }
    if (t == 0) g_rowptr[N_NODES] = run;
}

// ---------------- scatter: x4 edges/thread + self-loop tail ----------------
__global__ void scatter_kernel(const int* __restrict__ ei) {
    int t = blockIdx.x * blockDim.x + threadIdx.x;
    if (t < EQ) {
        int4 s = *(const int4*)(ei + t * 4);
        int4 d = *(const int4*)(ei + N_EDGES + t * 4);
        int p0 = atomicAdd(&g_cursor[d.x], 1);
        int p1 = atomicAdd(&g_cursor[d.y], 1);
        int p2 = atomicAdd(&g_cursor[d.z], 1);
        int p3 = atomicAdd(&g_cursor[d.w], 1);
        g_csrc[p0] = s.x; g_csrc[p1] = s.y; g_csrc[p2] = s.z; g_csrc[p3] = s.w;
    } else {
        int v = t - EQ;
        if (v < N_NODES) {
            int p = atomicAdd(&g_cursor[v], 1);
            g_csrc[p] = v;
        }
    }
}

// -------- fused GEMM: h = relu(A)@W (fp16 out) + asrc/adst epilogue --------
__global__ __launch_bounds__(256, 2) void gemm_fused(const float* __restrict__ A_ext,
                                                     const float* __restrict__ W,
                                                     const float* __restrict__ av,
                                                     const float* __restrict__ adv) {
    const float* __restrict__ A = A_ext ? A_ext : g_agg;
    __shared__ float As[128 * 36];
    __shared__ float Ws[32 * 132];
    const int tid = threadIdx.x;
    const int row0 = blockIdx.x * 128;
    const int tx = tid & 15, ty = tid >> 4;

    unsigned long long acc2[8][4];
#pragma unroll
    for (int i = 0; i < 8; i++)
#pragma unroll
        for (int j = 0; j < 4; j++) acc2[i][j] = 0ull;

    for (int k0 = 0; k0 < 128; k0 += 32) {
#pragma unroll
        for (int i = 0; i < 4; i++) {
            int f = tid + i * 256;
            int r = f >> 3, kq = f & 7;
            int gr = row0 + r;
            float4 v = make_float4(0.f, 0.f, 0.f, 0.f);
            if (gr < N_NODES) v = *(const float4*)(A + (size_t)gr * HID + k0 + kq * 4);
            v.x = fmaxf(v.x, 0.f); v.y = fmaxf(v.y, 0.f);
            v.z = fmaxf(v.z, 0.f); v.w = fmaxf(v.w, 0.f);
            *(float4*)(&As[r * 36 + kq * 4]) = v;
        }
#pragma unroll
        for (int i = 0; i < 4; i++) {
            int f = tid + i * 256;
            int kk = f >> 5, cq = f & 31;
            float4 v = *(const float4*)(W + (size_t)(k0 + kk) * HID + cq * 4);
            *(float4*)(&Ws[kk * 132 + cq * 4]) = v;
        }
        __syncthreads();
#pragma unroll
        for (int k = 0; k < 32; k++) {
            float4 b0 = *(const float4*)(&Ws[k * 132 + tx * 4]);
            float4 b1 = *(const float4*)(&Ws[k * 132 + 64 + tx * 4]);
            unsigned long long bb[4];
            bb[0] = pack2(b0.x, b0.y); bb[1] = pack2(b0.z, b0.w);
            bb[2] = pack2(b1.x, b1.y); bb[3] = pack2(b1.z, b1.w);
#pragma unroll
            for (int i = 0; i < 8; i++) {
                float a = (i < 4) ? As[(ty * 4 + i) * 36 + k]
                                  : As[(64 + ty * 4 + (i - 4)) * 36 + k];
                unsigned long long aa = pack2(a, a);
#pragma unroll
                for (int j = 0; j < 4; j++) acc2[i][j] = fma2(aa, bb[j], acc2[i][j]);
            }
        }
        __syncthreads();
    }

    float4 a1lo = *(const float4*)(av + tx * 4);
    float4 a1hi = *(const float4*)(av + 64 + tx * 4);
    float4 a2lo = *(const float4*)(adv + tx * 4);
    float4 a2hi = *(const float4*)(adv + 64 + tx * 4);
    const unsigned fullm = 0xffffffffu;
#pragma unroll
    for (int i = 0; i < 8; i++) {
        int gr = row0 + ((i < 4) ? (ty * 4 + i) : (64 + ty * 4 + (i - 4)));
        float c0, c1, c2, c3, c4, c5, c6, c7;
        unpack2(acc2[i][0], c0, c1); unpack2(acc2[i][1], c2, c3);
        unpack2(acc2[i][2], c4, c5); unpack2(acc2[i][3], c6, c7);
        float s1 = c0 * a1lo.x + c1 * a1lo.y + c2 * a1lo.z + c3 * a1lo.w
                 + c4 * a1hi.x + c5 * a1hi.y + c6 * a1hi.z + c7 * a1hi.w;
        float s2 = c0 * a2lo.x + c1 * a2lo.y + c2 * a2lo.z + c3 * a2lo.w
                 + c4 * a2hi.x + c5 * a2hi.y + c6 * a2hi.z + c7 * a2hi.w;
#pragma unroll
        for (int o = 8; o; o >>= 1) {
            s1 += __shfl_xor_sync(fullm, s1, o);
            s2 += __shfl_xor_sync(fullm, s2, o);
        }
        if (gr < N_NODES) {
            if (tx == 0) { g_asrc[gr] = s1; g_adst[gr] = s2; }
            __half2 h0 = __floats2half2_rn(c0, c1);
            __half2 h1 = __floats2half2_rn(c2, c3);
            __half2 h2 = __floats2half2_rn(c4, c5);
            __half2 h3 = __floats2half2_rn(c6, c7);
            uint2 u0 = make_uint2(*(unsigned*)&h0, *(unsigned*)&h1);
            uint2 u1 = make_uint2(*(unsigned*)&h2, *(unsigned*)&h3);
            *(uint2*)(g_hh + (size_t)gr * HID + tx * 4)      = u0;
            *(uint2*)(g_hh + (size_t)gr * HID + 64 + tx * 4) = u1;
        }
    }
}

// ------ GAT aggregation: warp/node, 2-pass softmax, shared logits/weights --
__global__ __launch_bounds__(256) void gat_agg_kernel(const float* __restrict__ bias,
                                                      const int* __restrict__ batch,
                                                      int pool_mode) {
    __shared__ float shw[8][DEG_CAP];
    int w = (blockIdx.x * blockDim.x + threadIdx.x) >> 5;
    int lane = threadIdx.x & 31;
    int wid = (threadIdx.x >> 5) & 7;
    if (w >= N_NODES) return;
    int beg = g_rowptr[w], end = g_rowptr[w + 1];
    int n = end - beg;
    float ad = g_adst[w];
    bool small = (n <= DEG_CAP);

    // pass A: compute leaky logits, stash in shared, track max
    float m = -CUDART_INF_F;
    for (int i = lane; i < n; i += 32) {
        int s = g_csrc[beg + i];
        float l = g_asrc[s] + ad;
        l = l > 0.f ? l : 0.2f * l;
        if (small) shw[wid][i] = l;
        m = fmaxf(m, l);
    }
#pragma unroll
    for (int o = 16; o; o >>= 1) m = fmaxf(m, __shfl_xor_sync(0xffffffffu, m, o));

    // pass B: exp from shared logits (no random reloads), sum, write back e
    float ssum = 0.f;
    if (small) {
        for (int i = lane; i < n; i += 32) {
            float e = __expf(shw[wid][i] - m);
            ssum += e;
            shw[wid][i] = e;
        }
    } else {
        for (int i = lane; i < n; i += 32) {
            int s = g_csrc[beg + i];
            float l = g_asrc[s] + ad;
            l = l > 0.f ? l : 0.2f * l;
            ssum += __expf(l - m);
        }
    }
#pragma unroll
    for (int o = 16; o; o >>= 1) ssum += __shfl_xor_sync(0xffffffffu, ssum, o);
    float inv = 1.f / ssum;
    __syncwarp();

    // phase 2: gather Σ e * h[src]  (scale by inv once at the end)
    float4 acc = make_float4(0.f, 0.f, 0.f, 0.f);
    const int col = lane << 2;
    if (small) {
        int i = 0;
        for (; i + 4 <= n; i += 4) {
            int s0 = g_csrc[beg + i + 0];
            int s1 = g_csrc[beg + i + 1];
            int s2 = g_csrc[beg + i + 2];
            int s3 = g_csrc[beg + i + 3];
            float e0 = shw[wid][i + 0], e1 = shw[wid][i + 1];
            float e2 = shw[wid][i + 2], e3 = shw[wid][i + 3];
            uint2 u0 = *(const uint2*)(g_hh + (size_t)s0 * HID + col);
            uint2 u1 = *(const uint2*)(g_hh + (size_t)s1 * HID + col);
            uint2 u2 = *(const uint2*)(g_hh + (size_t)s2 * HID + col);
            uint2 u3 = *(const uint2*)(g_hh + (size_t)s3 * HID + col);
            float2 f0a = __half22float2(*(__half2*)&u0.x), f0b = __half22float2(*(__half2*)&u0.y);
            float2 f1a = __half22float2(*(__half2*)&u1.x), f1b = __half22float2(*(__half2*)&u1.y);
            float2 f2a = __half22float2(*(__half2*)&u2.x), f2b = __half22float2(*(__half2*)&u2.y);
            float2 f3a = __half22float2(*(__half2*)&u3.x), f3b = __half22float2(*(__half2*)&u3.y);
            acc.x = fmaf(e0, f0a.x, acc.x); acc.y = fmaf(e0, f0a.y, acc.y);
            acc.z = fmaf(e0, f0b.x, acc.z); acc.w = fmaf(e0, f0b.y, acc.w);
            acc.x = fmaf(e1, f1a.x, acc.x); acc.y = fmaf(e1, f1a.y, acc.y);
            acc.z = fmaf(e1, f1b.x, acc.z); acc.w = fmaf(e1, f1b.y, acc.w);
            acc.x = fmaf(e2, f2a.x, acc.x); acc.y = fmaf(e2, f2a.y, acc.y);
            acc.z = fmaf(e2, f2b.x, acc.z); acc.w = fmaf(e2, f2b.y, acc.w);
            acc.x = fmaf(e3, f3a.x, acc.x); acc.y = fmaf(e3, f3a.y, acc.y);
            acc.z = fmaf(e3, f3b.x, acc.z); acc.w = fmaf(e3, f3b.y, acc.w);
        }
        for (; i < n; i++) {
            int s = g_csrc[beg + i];
            float e = shw[wid][i];
            uint2 u = *(const uint2*)(g_hh + (size_t)s * HID + col);
            float2 fa = __half22float2(*(__half2*)&u.x);
            float2 fb = __half22float2(*(__half2*)&u.y);
            acc.x = fmaf(e, fa.x, acc.x); acc.y = fmaf(e, fa.y, acc.y);
            acc.z = fmaf(e, fb.x, acc.z); acc.w = fmaf(e, fb.y, acc.w);
        }
    } else {  // rare high-degree path
        for (int i = 0; i < n; i++) {
            int s = g_csrc[beg + i];
            float l = g_asrc[s] + ad;
            l = l > 0.f ? l : 0.2f * l;
            float e = __expf(l - m);
            uint2 u = *(const uint2*)(g_hh + (size_t)s * HID + col);
            float2 fa = __half22float2(*(__half2*)&u.x);
            float2 fb = __half22float2(*(__half2*)&u.y);
            acc.x = fmaf(e, fa.x, acc.x); acc.y = fmaf(e, fa.y, acc.y);
            acc.z = fmaf(e, fb.x, acc.z); acc.w = fmaf(e, fb.y, acc.w);
        }
    }
    float4 bv = *(const float4*)(bias + col);
    acc.x = fmaf(acc.x, inv, bv.x);
    acc.y = fmaf(acc.y, inv, bv.y);
    acc.z = fmaf(acc.z, inv, bv.z);
    acc.w = fmaf(acc.w, inv, bv.w);

    if (!pool_mode) {
        *(float4*)(&g_agg[(size_t)w * HID + col]) = acc;
    } else {
        acc.x = fmaxf(acc.x, 0.f); acc.y = fmaxf(acc.y, 0.f);
        acc.z = fmaxf(acc.z, 0.f); acc.w = fmaxf(acc.w, 0.f);
        int g = batch[w];
        int base = g * HID + col;
        atomicMax((int*)&g_maxp[base + 0], __float_as_int(acc.x));
        atomicMax((int*)&g_maxp[base + 1], __float_as_int(acc.y));
        atomicMax((int*)&g_maxp[base + 2], __float_as_int(acc.z));
        atomicMax((int*)&g_maxp[base + 3], __float_as_int(acc.w));
        atomicAdd(&g_sump[base + 0], acc.x);
        atomicAdd(&g_sump[base + 1], acc.y);
        atomicAdd(&g_sump[base + 2], acc.z);
        atomicAdd(&g_sump[base + 3], acc.w);
        if (lane == 0) atomicAdd(&g_cnt[g], 1);
    }
}

__global__ void final_kernel(const float* __restrict__ fcw, const float* __restrict__ fcb,
                             float* __restrict__ out) {
    int w = (blockIdx.x * blockDim.x + threadIdx.x) >> 5;
    int lane = threadIdx.x & 31;
    if (w >= NG) return;
    float4 mx = *(const float4*)(&g_maxp[w * HID + (lane << 2)]);
    float4 sm = *(const float4*)(&g_sump[w * HID + (lane << 2)]);
    float4 w1 = *(const float4*)(fcw + (lane << 2));
    float4 w2 = *(const float4*)(fcw + HID + (lane << 2));
    float c = fmaxf((float)g_cnt[w], 1.f);
    float p = mx.x * w1.x + mx.y * w1.y + mx.z * w1.z + mx.w * w1.w
            + (sm.x * w2.x + sm.y * w2.y + sm.z * w2.z + sm.w * w2.w) / c;
#pragma unroll
    for (int o = 16; o; o >>= 1) p += __shfl_xor_sync(0xffffffffu, p, o);
    if (lane == 0) out[w] = p + fcb[0];
}

// ---------------- launch (CSR chain forked to overlap with GEMM1) ----------
extern "C" void kernel_launch(void* const* d_in, const int* in_sizes, int n_in,
                              void* d_out, int out_size) {
    const float* x   = (const float*)d_in[0];
    const int*   ei  = (const int*)d_in[1];
    const int*   bat = (const int*)d_in[2];
    const float* W1  = (const float*)d_in[3];
    const float* as1 = (const float*)d_in[4];
    const float* ad1 = (const float*)d_in[5];
    const float* b1  = (const float*)d_in[6];
    const float* W2  = (const float*)d_in[7];
    const float* as2 = (const float*)d_in[8];
    const float* ad2 = (const float*)d_in[9];
    const float* b2  = (const float*)d_in[10];
    const float* fcw = (const float*)d_in[11];
    const float* fcb = (const float*)d_in[12];
    float* out = (float*)d_out;

    const int TB = 256;
    const int initBlocks = (NG * HID + TB - 1) / TB;
    const int histBlocks = (EQ + TB - 1) / TB;
    const int scatBlocks = (EQ + N_NODES + TB - 1) / TB;
    const int warpNodeBlocks = (N_NODES * 32 + TB - 1) / TB;
    const int gemmBlocks = (N_NODES + 127) / 128;

    // fork: CSR chain on s2, GEMM1 on capture stream (independent subgraphs)
    cudaStream_t s2;
    cudaEvent_t ev0, ev1;
    cudaStreamCreateWithFlags(&s2, cudaStreamNonBlocking);
    cudaEventCreateWithFlags(&ev0, cudaEventDisableTiming);
    cudaEventCreateWithFlags(&ev1, cudaEventDisableTiming);

    cudaEventRecord(ev0, 0);
    cudaStreamWaitEvent(s2, ev0, 0);

    init_kernel<<<initBlocks, TB, 0, s2>>>();         // 1
    hist_kernel<<<histBlocks, TB, 0, s2>>>(ei);       // 2
    scan_kernel<<<1, 1024, 0, s2>>>();                // 3
    scatter_kernel<<<scatBlocks, TB, 0, s2>>>(ei);    // 4 (profiler slot)

    gemm_fused<<<gemmBlocks, TB>>>(x, W1, as1, ad1);  // 5, concurrent with CSR

    cudaEventRecord(ev1, s2);
    cudaStreamWaitEvent(0, ev1, 0);                   // join

    gat_agg_kernel<<<warpNodeBlocks, TB>>>(b1, bat, 0);    // 6
    gemm_fused<<<gemmBlocks, TB>>>(nullptr, W2, as2, ad2); // 7
    gat_agg_kernel<<<warpNodeBlocks, TB>>>(b2, bat, 1);    // 8
    final_kernel<<<(NG * 32 + TB - 1) / TB, TB>>>(fcw, fcb, out); // 9
    // streams/events intentionally not destroyed during potential capture;
    // kernel_launch is invoked only a handful of times (host objects, no device mem)
}